// round 5
// baseline (speedup 1.0000x reference)
#include <cuda_runtime.h>
#include <cuda_fp16.h>
#include <stdint.h>
#include <math.h>

// ---------------- problem constants ----------------
#define MDIM 16384      // B*S
#define NDIM 2048       // F
#define KDIM 2048       // D
#define TM   128        // CTA tile M
#define TN   128        // CTA tile N
#define TKC  32         // K per pipeline stage
#define KITERS (KDIM/TKC)   // 64
#define EPSV 1e-6f

// SMEM per stage: Ah | Al | Bh | Bl, each 128 rows x 32 halves, rows padded to 80B
#define ROWB   80
#define AH_OFF 0
#define AL_OFF (128*ROWB)        // 10240
#define BH_OFF (2*128*ROWB)      // 20480
#define BL_OFF (3*128*ROWB)      // 30720
#define STAGE_BYTES (4*128*ROWB) // 40960
#define SMEM_BYTES  (2*STAGE_BYTES)  // 81920  -> 2 CTAs/SM

// ---------------- scratch ----------------
__device__ __half g_x_hi[33554432];
__device__ __half g_x_lo[33554432];
__device__ __half g_w_hi[4194304];
__device__ __half g_w_lo[4194304];
__device__ float  g_x_sq[MDIM];
__device__ float  g_w_sq[NDIM];

// ---------------- PTX helpers ----------------
__device__ __forceinline__ uint32_t smem_u32(const void* p) {
    uint32_t r;
    asm("{ .reg .u64 t; cvta.to.shared.u64 t, %1; cvt.u32.u64 %0, t; }" : "=r"(r) : "l"(p));
    return r;
}
__device__ __forceinline__ void cp16(uint32_t dst, const void* src) {
    asm volatile("cp.async.cg.shared.global [%0], [%1], 16;" :: "r"(dst), "l"(src) : "memory");
}
__device__ __forceinline__ void cp_commit() {
    asm volatile("cp.async.commit_group;" ::: "memory");
}
template <int N>
__device__ __forceinline__ void cp_wait() {
    asm volatile("cp.async.wait_group %0;" :: "n"(N) : "memory");
}
__device__ __forceinline__ void ldsm4(uint32_t* r, uint32_t addr) {
    asm volatile("ldmatrix.sync.aligned.m8n8.x4.shared.b16 {%0,%1,%2,%3}, [%4];"
        : "=r"(r[0]), "=r"(r[1]), "=r"(r[2]), "=r"(r[3]) : "r"(addr));
}
// m16n8k16 row.col f16 -> f32
__device__ __forceinline__ void mma16816(float* c, const uint32_t* a, uint32_t b0, uint32_t b1) {
    asm volatile(
        "mma.sync.aligned.m16n8k16.row.col.f32.f16.f16.f32 "
        "{%0,%1,%2,%3}, {%4,%5,%6,%7}, {%8,%9}, {%0,%1,%2,%3};"
        : "+f"(c[0]), "+f"(c[1]), "+f"(c[2]), "+f"(c[3])
        : "r"(a[0]), "r"(a[1]), "r"(a[2]), "r"(a[3]), "r"(b0), "r"(b1));
}

// ---------------- pre-pass: fp32 -> (hi,lo) fp16 split + row sum-of-squares ----
__global__ __launch_bounds__(256) void split_kernel(const float* __restrict__ x,
                                                    const float* __restrict__ w) {
    int row = blockIdx.x;
    const float* src;
    __half *hi, *lo;
    float* sq;
    if (row < MDIM) {
        src = x + (size_t)row * KDIM;
        hi = g_x_hi + (size_t)row * KDIM;
        lo = g_x_lo + (size_t)row * KDIM;
        sq = g_x_sq + row;
    } else {
        int r = row - MDIM;
        src = w + (size_t)r * KDIM;
        hi = g_w_hi + (size_t)r * KDIM;
        lo = g_w_lo + (size_t)r * KDIM;
        sq = g_w_sq + r;
    }
    float acc = 0.f;
    for (int j = threadIdx.x * 4; j < KDIM; j += 256 * 4) {
        float4 v = *reinterpret_cast<const float4*>(src + j);
        __half h0 = __float2half_rn(v.x), h1 = __float2half_rn(v.y);
        __half h2 = __float2half_rn(v.z), h3 = __float2half_rn(v.w);
        __half l0 = __float2half_rn(v.x - __half2float(h0));
        __half l1 = __float2half_rn(v.y - __half2float(h1));
        __half l2 = __float2half_rn(v.z - __half2float(h2));
        __half l3 = __float2half_rn(v.w - __half2float(h3));
        *reinterpret_cast<__half2*>(hi + j)     = __halves2half2(h0, h1);
        *reinterpret_cast<__half2*>(hi + j + 2) = __halves2half2(h2, h3);
        *reinterpret_cast<__half2*>(lo + j)     = __halves2half2(l0, l1);
        *reinterpret_cast<__half2*>(lo + j + 2) = __halves2half2(l2, l3);
        acc += v.x * v.x + v.y * v.y + v.z * v.z + v.w * v.w;
    }
    __shared__ float red[8];
    #pragma unroll
    for (int o = 16; o > 0; o >>= 1) acc += __shfl_xor_sync(0xffffffffu, acc, o);
    if ((threadIdx.x & 31) == 0) red[threadIdx.x >> 5] = acc;
    __syncthreads();
    if (threadIdx.x < 8) {
        float v = red[threadIdx.x];
        #pragma unroll
        for (int o = 4; o > 0; o >>= 1) v += __shfl_xor_sync(0xffu, v, o);
        if (threadIdx.x == 0) *sq = v;
    }
}

// ---------------- main GEMM + Yat epilogue ----------------
// grid = (MDIM/TM)*(NDIM/TN) = 128*16 = 2048, block = 256 (8 warps: 2 along M x 4 along N),
// warp tile 64x32, 2 CTAs per SM.
__global__ __launch_bounds__(256, 2) void yat_gemm(float* __restrict__ out,
                                                   const float* __restrict__ alpha,
                                                   const float* __restrict__ bias) {
    extern __shared__ char smem[];
    const uint32_t smem_base = smem_u32(smem);

    const int tid = threadIdx.x;
    const int mtile = blockIdx.x >> 4;
    const int ntile = blockIdx.x & 15;
    const int m0 = mtile * TM;
    const int n0 = ntile * TN;

    const __half* xh = g_x_hi + (size_t)m0 * KDIM;
    const __half* xl = g_x_lo + (size_t)m0 * KDIM;
    const __half* wh = g_w_hi + (size_t)n0 * KDIM;
    const __half* wl = g_w_lo + (size_t)n0 * KDIM;

    // ---- stage loader: 4 matrices x 128 rows x 64B = 2048 x 16B chunks / 256 thr ----
    auto load_stage = [&](int i) {
        const uint32_t sb = smem_base + (uint32_t)(i & 1) * STAGE_BYTES;
        const int kk = i * TKC;
        #pragma unroll
        for (int half = 0; half < 2; half++) {
            int q = tid + 256 * half;
            int r = q >> 2, c = q & 3;
            uint32_t so = (uint32_t)r * ROWB + (uint32_t)c * 16;
            size_t go = (size_t)r * KDIM + kk + c * 8;
            cp16(sb + AH_OFF + so, xh + go);
            cp16(sb + AL_OFF + so, xl + go);
            cp16(sb + BH_OFF + so, wh + go);
            cp16(sb + BL_OFF + so, wl + go);
        }
    };

    // ---- warp/lane geometry ----
    const int warp = tid >> 5;
    const int lane = tid & 31;
    const int wm = warp & 1;        // 2 warps along M (64 rows each)
    const int wn = warp >> 1;       // 4 warps along N (32 cols each)

    // ldmatrix per-lane base offsets (within a stage)
    // A (row-major m16k16 frags): lanes 0-15 -> rows 0-15 @k0, lanes 16-31 -> rows @k+8
    const uint32_t a_loff = (uint32_t)(wm * 64 + (lane & 15)) * ROWB
                          + (uint32_t)(lane >> 4) * 16;
    // B (n-major rows over k): one x4 covers 2 n-groups of 8
    const uint32_t b_loff = (uint32_t)(wn * 32 + (lane & 7) + ((lane >> 4) & 1) * 8) * ROWB
                          + (uint32_t)((lane >> 3) & 1) * 16;

    float acc[4][4][4];
    #pragma unroll
    for (int mi = 0; mi < 4; mi++)
        #pragma unroll
        for (int ni = 0; ni < 4; ni++)
            #pragma unroll
            for (int e = 0; e < 4; e++) acc[mi][ni][e] = 0.f;

    load_stage(0);
    cp_commit();

    for (int i = 0; i < KITERS; i++) {
        if (i + 1 < KITERS) {
            load_stage(i + 1);
            cp_commit();
            cp_wait<1>();
        } else {
            cp_wait<0>();
        }
        __syncthreads();

        const uint32_t sb = smem_base + (uint32_t)(i & 1) * STAGE_BYTES;
        const uint32_t aAh = sb + AH_OFF + a_loff;
        const uint32_t aAl = sb + AL_OFF + a_loff;
        const uint32_t aBh = sb + BH_OFF + b_loff;
        const uint32_t aBl = sb + BL_OFF + b_loff;

        #pragma unroll
        for (int ks = 0; ks < 2; ks++) {
            const uint32_t kb = ks * 32;    // 16 halves per k-step
            uint32_t Bh[2][4], Bl[2][4];
            ldsm4(Bh[0], aBh + kb);
            ldsm4(Bh[1], aBh + 16 * ROWB + kb);
            ldsm4(Bl[0], aBl + kb);
            ldsm4(Bl[1], aBl + 16 * ROWB + kb);
            {
                uint32_t Ah[4][4];
                #pragma unroll
                for (int mi = 0; mi < 4; mi++)
                    ldsm4(Ah[mi], aAh + (uint32_t)mi * (16 * ROWB) + kb);
                #pragma unroll
                for (int ni = 0; ni < 4; ni++) {
                    uint32_t b0 = Bh[ni >> 1][(ni & 1) * 2];
                    uint32_t b1 = Bh[ni >> 1][(ni & 1) * 2 + 1];
                    #pragma unroll
                    for (int mi = 0; mi < 4; mi++)
                        mma16816(acc[mi][ni], Ah[mi], b0, b1);     // x_hi * w_hi
                }
                #pragma unroll
                for (int ni = 0; ni < 4; ni++) {
                    uint32_t b0 = Bl[ni >> 1][(ni & 1) * 2];
                    uint32_t b1 = Bl[ni >> 1][(ni & 1) * 2 + 1];
                    #pragma unroll
                    for (int mi = 0; mi < 4; mi++)
                        mma16816(acc[mi][ni], Ah[mi], b0, b1);     // x_hi * w_lo
                }
            }
            {
                uint32_t Al[4][4];
                #pragma unroll
                for (int mi = 0; mi < 4; mi++)
                    ldsm4(Al[mi], aAl + (uint32_t)mi * (16 * ROWB) + kb);
                #pragma unroll
                for (int ni = 0; ni < 4; ni++) {
                    uint32_t b0 = Bh[ni >> 1][(ni & 1) * 2];
                    uint32_t b1 = Bh[ni >> 1][(ni & 1) * 2 + 1];
                    #pragma unroll
                    for (int mi = 0; mi < 4; mi++)
                        mma16816(acc[mi][ni], Al[mi], b0, b1);     // x_lo * w_hi
                }
            }
        }
        __syncthreads();
    }

    // ---- epilogue: Yat transform from register accumulators ----
    const int g  = lane >> 2;
    const int tg = lane & 3;
    const float a = *alpha;
    const float base = sqrtf((float)NDIM) / logf(1.0f + (float)NDIM);
    const float scale = powf(base, a);

    #pragma unroll
    for (int mi = 0; mi < 4; mi++) {
        const int r0 = m0 + wm * 64 + mi * 16 + g;
        const float xs0 = g_x_sq[r0];
        const float xs1 = g_x_sq[r0 + 8];
        #pragma unroll
        for (int ni = 0; ni < 4; ni++) {
            const int col = n0 + wn * 32 + ni * 8 + tg * 2;
            const float ws0 = __ldg(&g_w_sq[col]);
            const float ws1 = __ldg(&g_w_sq[col + 1]);
            const float bi0 = __ldg(&bias[col]);
            const float bi1 = __ldg(&bias[col + 1]);
            float y;
            float2 o;
            y = acc[mi][ni][0];
            o.x = scale * y * y / (xs0 + ws0 - 2.0f * y + EPSV) + bi0;
            y = acc[mi][ni][1];
            o.y = scale * y * y / (xs0 + ws1 - 2.0f * y + EPSV) + bi1;
            *reinterpret_cast<float2*>(out + (size_t)r0 * NDIM + col) = o;
            y = acc[mi][ni][2];
            o.x = scale * y * y / (xs1 + ws0 - 2.0f * y + EPSV) + bi0;
            y = acc[mi][ni][3];
            o.y = scale * y * y / (xs1 + ws1 - 2.0f * y + EPSV) + bi1;
            *reinterpret_cast<float2*>(out + (size_t)(r0 + 8) * NDIM + col) = o;
        }
    }
}

// ---------------- launch ----------------
extern "C" void kernel_launch(void* const* d_in, const int* in_sizes, int n_in,
                              void* d_out, int out_size) {
    (void)in_sizes; (void)n_in; (void)out_size;
    const float* x     = (const float*)d_in[0];
    const float* w     = (const float*)d_in[1];
    const float* alpha = (const float*)d_in[2];
    const float* bias  = (const float*)d_in[3];
    float* out = (float*)d_out;

    static int smem_set = 0;
    if (!smem_set) {
        cudaFuncSetAttribute(yat_gemm, cudaFuncAttributeMaxDynamicSharedMemorySize, SMEM_BYTES);
        smem_set = 1;
    }

    split_kernel<<<MDIM + NDIM, 256>>>(x, w);
    yat_gemm<<<(MDIM / TM) * (NDIM / TN), 256, SMEM_BYTES>>>(out, alpha, bias);
}